// round 1
// baseline (speedup 1.0000x reference)
#include <cuda_runtime.h>
#include <math.h>

// Problem dims (fixed per reference)
#define BSZ 512
#define FD  512
#define HD  512
#define ED  8
#define OD  512

// Scratch (device globals; no allocation allowed)
__device__ float d_h1[BSZ * HD];
__device__ float d_h2[BSZ * HD];
__device__ float d_g [BSZ * ED];
__device__ float d_T [ED * BSZ * HD];
__device__ float d_e1[BSZ * HD];
__device__ float d_e2[BSZ * HD];

__device__ __forceinline__ float elu1(float v) {
    return v > 0.f ? v : expm1f(v);
}

// C[m,n] = act( sum_k A[m,k]*B[n,k] + bias[n] )
// A: [M,K] row-major, B: [N,K] row-major (NT GEMM). Batched over blockIdx.z:
// Bm += z*strideB, C += z*strideC.
// Tiles: 64x64x16, 256 threads, 4x4 per thread.
__global__ void __launch_bounds__(256)
sgemm_nt(const float* __restrict__ A, const float* __restrict__ Bm,
         const float* __restrict__ bias, float* __restrict__ C,
         int M, int N, int K, long strideB, long strideC, int doElu)
{
    const int e = blockIdx.z;
    Bm += (long)e * strideB;
    C  += (long)e * strideC;

    __shared__ float As[16][64 + 4];
    __shared__ float Bs[16][64 + 4];

    const int tid = threadIdx.x;
    const int tx = tid & 15;        // n direction (16 threads)
    const int ty = tid >> 4;        // m direction (16 threads)
    const int bm = blockIdx.y * 64;
    const int bn = blockIdx.x * 64;

    // loader: each thread brings one float4 of A and one of B per K-tile
    const int lr = tid >> 2;         // 0..63: row within tile
    const int lk = (tid & 3) * 4;    // 0,4,8,12: k offset

    float acc[4][4] = {};

    for (int k0 = 0; k0 < K; k0 += 16) {
        float4 a4 = *(const float4*)&A [(long)(bm + lr) * K + k0 + lk];
        float4 b4 = *(const float4*)&Bm[(long)(bn + lr) * K + k0 + lk];
        As[lk + 0][lr] = a4.x; As[lk + 1][lr] = a4.y;
        As[lk + 2][lr] = a4.z; As[lk + 3][lr] = a4.w;
        Bs[lk + 0][lr] = b4.x; Bs[lk + 1][lr] = b4.y;
        Bs[lk + 2][lr] = b4.z; Bs[lk + 3][lr] = b4.w;
        __syncthreads();

        #pragma unroll
        for (int kk = 0; kk < 16; kk++) {
            float ar[4], br[4];
            #pragma unroll
            for (int i = 0; i < 4; i++) ar[i] = As[kk][ty * 4 + i];
            #pragma unroll
            for (int j = 0; j < 4; j++) br[j] = Bs[kk][tx * 4 + j];
            #pragma unroll
            for (int i = 0; i < 4; i++)
                #pragma unroll
                for (int j = 0; j < 4; j++)
                    acc[i][j] = fmaf(ar[i], br[j], acc[i][j]);
        }
        __syncthreads();
    }

    #pragma unroll
    for (int i = 0; i < 4; i++) {
        int m = bm + ty * 4 + i;
        #pragma unroll
        for (int j = 0; j < 4; j++) {
            int n = bn + tx * 4 + j;
            float v = acc[i][j];
            if (bias) v += bias[n];
            if (doElu) v = elu1(v);
            C[(long)m * N + n] = v;
        }
    }
}

// logits = h @ gw2.T + gb2 ; g = softmax(logits, axis=1). One block per batch row.
__global__ void __launch_bounds__(256)
gate_kernel(const float* __restrict__ h, const float* __restrict__ w2,
            const float* __restrict__ b2, float* __restrict__ g)
{
    __shared__ float s[512];
    __shared__ float lg[8];
    const int b = blockIdx.x, tid = threadIdx.x;
    for (int i = tid; i < 512; i += 256) s[i] = h[(long)b * 512 + i];
    __syncthreads();

    const int w = tid >> 5, lane = tid & 31;   // 8 warps, warp w -> expert w
    float sum = 0.f;
    for (int i = lane; i < 512; i += 32) sum += s[i] * w2[(long)w * 512 + i];
    #pragma unroll
    for (int o = 16; o > 0; o >>= 1) sum += __shfl_xor_sync(0xffffffffu, sum, o);
    if (lane == 0) lg[w] = sum + b2[w];
    __syncthreads();

    if (tid == 0) {
        float mx = lg[0];
        #pragma unroll
        for (int i = 1; i < 8; i++) mx = fmaxf(mx, lg[i]);
        float ex[8], se = 0.f;
        #pragma unroll
        for (int i = 0; i < 8; i++) { ex[i] = expf(lg[i] - mx); se += ex[i]; }
        float inv = 1.f / se;
        #pragma unroll
        for (int i = 0; i < 8; i++) g[(long)b * 8 + i] = ex[i] * inv;
    }
}

// out[b,h] = act( sum_e g[b,e] * (T[e,b,h] + beta[e,h]) )
__global__ void __launch_bounds__(256)
blend_kernel(const float* __restrict__ T, const float* __restrict__ g,
             const float* __restrict__ beta, float* __restrict__ out, int doElu)
{
    const int idx = blockIdx.x * 256 + threadIdx.x;   // 512*512 elems
    const int b = idx >> 9, h = idx & 511;
    float sum = 0.f;
    #pragma unroll
    for (int e = 0; e < 8; e++)
        sum += g[b * 8 + e] * (T[((long)e << 18) + idx] + beta[e * 512 + h]);
    out[idx] = doElu ? elu1(sum) : sum;
}

extern "C" void kernel_launch(void* const* d_in, const int* in_sizes, int n_in,
                              void* d_out, int out_size)
{
    const float* x      = (const float*)d_in[0];
    const float* gw0    = (const float*)d_in[1];
    const float* gb0    = (const float*)d_in[2];
    const float* gw1    = (const float*)d_in[3];
    const float* gb1    = (const float*)d_in[4];
    const float* gw2    = (const float*)d_in[5];
    const float* gb2    = (const float*)d_in[6];
    const float* alpha0 = (const float*)d_in[7];
    const float* beta0  = (const float*)d_in[8];
    const float* alpha1 = (const float*)d_in[9];
    const float* beta1  = (const float*)d_in[10];
    const float* alpha2 = (const float*)d_in[11];
    const float* beta2  = (const float*)d_in[12];
    float* out = (float*)d_out;

    float *h1, *h2, *gp, *T, *e1, *e2;
    cudaGetSymbolAddress((void**)&h1, d_h1);
    cudaGetSymbolAddress((void**)&h2, d_h2);
    cudaGetSymbolAddress((void**)&gp, d_g);
    cudaGetSymbolAddress((void**)&T,  d_T);
    cudaGetSymbolAddress((void**)&e1, d_e1);
    cudaGetSymbolAddress((void**)&e2, d_e2);

    dim3 g1(8, 8, 1);   // 512x512 tiles of 64x64
    dim3 g8(8, 8, 8);   // batched over 8 experts
    const long sB = (long)HD * FD;   // 512*512 weight stride per expert
    const long sC = (long)BSZ * HD;  // 512*512 output stride per expert

    // gating MLP
    sgemm_nt<<<g1, 256>>>(x,  gw0, gb0, h1, BSZ, HD, FD, 0, 0, 1);
    sgemm_nt<<<g1, 256>>>(h1, gw1, gb1, h2, BSZ, HD, HD, 0, 0, 1);
    gate_kernel<<<BSZ, 256>>>(h2, gw2, gb2, gp);

    // expert layer 1: T[e] = x @ alpha0[e].T ; e1 = elu(blend + blended beta0)
    sgemm_nt<<<g8, 256>>>(x, alpha0, nullptr, T, BSZ, HD, FD, sB, sC, 0);
    blend_kernel<<<(BSZ * HD) / 256, 256>>>(T, gp, beta0, e1, 1);

    // expert layer 2
    sgemm_nt<<<g8, 256>>>(e1, alpha1, nullptr, T, BSZ, HD, HD, sB, sC, 0);
    blend_kernel<<<(BSZ * HD) / 256, 256>>>(T, gp, beta1, e2, 1);

    // expert layer 3 (no activation)
    sgemm_nt<<<g8, 256>>>(e2, alpha2, nullptr, T, BSZ, OD, HD, sB, sC, 0);
    blend_kernel<<<(BSZ * OD) / 256, 256>>>(T, gp, beta2, out, 0);
}

// round 3
// speedup vs baseline: 1.9268x; 1.9268x over previous
#include <cuda_runtime.h>
#include <cuda_bf16.h>
#include <math.h>
#include <cstdint>

#define BSZ 512
#define FD  512
#define HD  512
#define ED  8
#define OD  512

// ---------------- scratch (device globals; allocation is forbidden) ----------------
__device__ float d_h1[BSZ * HD];
__device__ float d_h2[BSZ * HD];
__device__ float d_g [BSZ * ED];
__device__ float d_T [ED * BSZ * HD];
__device__ float d_e1[BSZ * HD];
__device__ float d_e2[BSZ * HD];

__device__ __align__(16) __nv_bfloat16 d_xhi[BSZ * FD], d_xlo[BSZ * FD];
__device__ __align__(16) __nv_bfloat16 d_ahi[BSZ * FD], d_alo[BSZ * FD];
__device__ __align__(16) __nv_bfloat16 d_g0hi[HD * FD], d_g0lo[HD * FD];
__device__ __align__(16) __nv_bfloat16 d_g1hi[HD * HD], d_g1lo[HD * HD];
__device__ __align__(16) __nv_bfloat16 d_w0hi[ED * HD * FD], d_w0lo[ED * HD * FD];
__device__ __align__(16) __nv_bfloat16 d_w1hi[ED * HD * HD], d_w1lo[ED * HD * HD];
__device__ __align__(16) __nv_bfloat16 d_w2hi[ED * OD * HD], d_w2lo[ED * OD * HD];

__device__ __forceinline__ float elu1(float v) { return v > 0.f ? v : expm1f(v); }

__device__ __forceinline__ uint32_t smem_u32(const void* p) {
    uint32_t a;
    asm("{ .reg .u64 t; cvta.to.shared.u64 t, %1; cvt.u32.u64 %0, t; }" : "=r"(a) : "l"(p));
    return a;
}

#define CP16(dst, src) \
    asm volatile("cp.async.cg.shared.global [%0], [%1], 16;" :: "r"(dst), "l"(src))

#define LDSM4(r, addr) \
    asm volatile("ldmatrix.sync.aligned.m8n8.x4.shared.b16 {%0,%1,%2,%3}, [%4];" \
                 : "=r"((r)[0]), "=r"((r)[1]), "=r"((r)[2]), "=r"((r)[3]) : "r"(addr))

#define MMA16816(d, a, b0, b1) \
    asm volatile("mma.sync.aligned.m16n8k16.row.col.f32.bf16.bf16.f32 " \
                 "{%0,%1,%2,%3},{%4,%5,%6,%7},{%8,%9},{%0,%1,%2,%3};" \
                 : "+f"((d)[0]), "+f"((d)[1]), "+f"((d)[2]), "+f"((d)[3]) \
                 : "r"((a)[0]), "r"((a)[1]), "r"((a)[2]), "r"((a)[3]), "r"(b0), "r"(b1))

// ---------------- split-conversion: fp32 -> (hi, lo) bf16 ----------------
__global__ void __launch_bounds__(256)
conv_split(const float4* __restrict__ in, uint2* __restrict__ hi, uint2* __restrict__ lo, int n4) {
    int i = blockIdx.x * 256 + threadIdx.x;
    if (i >= n4) return;
    float4 v = in[i];
    __nv_bfloat16 h0 = __float2bfloat16(v.x), h1 = __float2bfloat16(v.y);
    __nv_bfloat16 h2 = __float2bfloat16(v.z), h3 = __float2bfloat16(v.w);
    __nv_bfloat16 l0 = __float2bfloat16(v.x - __bfloat162float(h0));
    __nv_bfloat16 l1 = __float2bfloat16(v.y - __bfloat162float(h1));
    __nv_bfloat16 l2 = __float2bfloat16(v.z - __bfloat162float(h2));
    __nv_bfloat16 l3 = __float2bfloat16(v.w - __bfloat162float(h3));
    uint2 H, L;
    H.x = (uint32_t)__bfloat16_as_ushort(h0) | ((uint32_t)__bfloat16_as_ushort(h1) << 16);
    H.y = (uint32_t)__bfloat16_as_ushort(h2) | ((uint32_t)__bfloat16_as_ushort(h3) << 16);
    L.x = (uint32_t)__bfloat16_as_ushort(l0) | ((uint32_t)__bfloat16_as_ushort(l1) << 16);
    L.y = (uint32_t)__bfloat16_as_ushort(l2) | ((uint32_t)__bfloat16_as_ushort(l3) << 16);
    hi[i] = H; lo[i] = L;
}

// ---------------- tensor-core split GEMM (mma.sync / ldmatrix / cp.async) ----------------
// C[m,n] = epi( sum_k x[m,k]*w[n,k] ), x = xhi+xlo, w = whi+wlo (3 hi/lo passes).
// M=N=K=512. CTA tile 128x128, BK=64, 3-stage cp.async pipeline, 8 warps (32x64 each).
__global__ void __launch_bounds__(256)
tgemm_mma(const __nv_bfloat16* __restrict__ xhi, const __nv_bfloat16* __restrict__ xlo,
          const __nv_bfloat16* __restrict__ whi, const __nv_bfloat16* __restrict__ wlo,
          const float* __restrict__ bias, float* __restrict__ C,
          long strideW, long strideC, int doEpi)
{
    extern __shared__ __align__(128) char smem[];
    const uint32_t sb = smem_u32(smem);
    const int tid = threadIdx.x;
    const int wid = tid >> 5, lane = tid & 31;
    const int e = blockIdx.z;
    const int bm = blockIdx.y * 128, bn = blockIdx.x * 128;
    whi += (long)e * strideW;
    wlo += (long)e * strideW;
    C   += (long)e * strideC;

    const __nv_bfloat16* Ap[3] = { xhi, xlo, xhi };
    const __nv_bfloat16* Bp[3] = { whi, whi, wlo };

    // global->smem loader lanes: per it, row = it*32 + tid/8, 16B chunk = tid%8
    const int lsub = tid >> 3;   // 0..31
    const int lc16 = tid & 7;

    // chunk c (0..23): phase = c/8 selects (hi,lo) pass; k0 = (c%8)*64
    auto load_chunk = [&](int c, int buf) {
        const int ph = c >> 3, k0 = (c & 7) << 6;
        const __nv_bfloat16* A = Ap[ph];
        const __nv_bfloat16* B = Bp[ph];
        const uint32_t base = sb + (uint32_t)buf * 32768u;
        #pragma unroll
        for (int it = 0; it < 4; it++) {
            const int row = it * 32 + lsub;
            const uint32_t dst = base + (uint32_t)(row * 128 + ((lc16 ^ (row & 7)) << 4));
            CP16(dst,           A + (long)(bm + row) * 512 + k0 + lc16 * 8);
            CP16(dst + 16384u,  B + (long)(bn + row) * 512 + k0 + lc16 * 8);
        }
    };

    // warp layout: 4 warps along M, 2 along N; warp tile 32(M) x 64(N)
    const int warpM = wid & 3, warpN = wid >> 2;
    const int arow = warpM * 32 + (lane & 15);      // ldmatrix A row (mi adds +16)
    const uint32_t aswz = (uint32_t)(arow & 7);
    const uint32_t ahi = (uint32_t)(lane >> 4);     // A 16B-chunk half select
    const int q = lane >> 3;                        // B quad
    const int brow_base = warpN * 64 + ((q >> 1) << 3) + (lane & 7);
    const uint32_t bk = (uint32_t)(q & 1);

    float acc[2][8][4] = {};

    load_chunk(0, 0);
    asm volatile("cp.async.commit_group;" ::: "memory");
    load_chunk(1, 1);
    asm volatile("cp.async.commit_group;" ::: "memory");

    for (int c = 0; c < 24; c++) {
        if (c < 23) asm volatile("cp.async.wait_group 1;" ::: "memory");
        else        asm volatile("cp.async.wait_group 0;" ::: "memory");
        __syncthreads();
        if (c + 2 < 24) {
            load_chunk(c + 2, (c + 2) % 3);
            asm volatile("cp.async.commit_group;" ::: "memory");
        }

        const uint32_t Ab = sb + (uint32_t)(c % 3) * 32768u;
        const uint32_t Bb = Ab + 16384u;
        #pragma unroll
        for (int ks = 0; ks < 4; ks++) {
            uint32_t a[2][4];
            #pragma unroll
            for (int mi = 0; mi < 2; mi++) {
                uint32_t addr = Ab + (uint32_t)((arow + mi * 16) * 128)
                              + ((((uint32_t)(ks << 1) + ahi) ^ aswz) << 4);
                LDSM4(a[mi], addr);
            }
            uint32_t b[4][4];
            #pragma unroll
            for (int np = 0; np < 4; np++) {
                const int brow = brow_base + np * 16;
                uint32_t addr = Bb + (uint32_t)(brow * 128)
                              + ((((uint32_t)(ks << 1) + bk) ^ (uint32_t)(brow & 7)) << 4);
                LDSM4(b[np], addr);
            }
            #pragma unroll
            for (int mi = 0; mi < 2; mi++)
                #pragma unroll
                for (int ni = 0; ni < 8; ni++)
                    MMA16816(acc[mi][ni], a[mi], b[ni >> 1][(ni & 1) * 2],
                             b[ni >> 1][(ni & 1) * 2 + 1]);
        }
        __syncthreads();
    }

    // epilogue: D-frag thread map: rows lane/4 (+8), cols (lane%4)*2 (+1)
    const int gr = lane >> 2, gc = (lane & 3) * 2;
    #pragma unroll
    for (int mi = 0; mi < 2; mi++) {
        const int row0 = bm + warpM * 32 + mi * 16 + gr;
        #pragma unroll
        for (int ni = 0; ni < 8; ni++) {
            const int col = bn + warpN * 64 + ni * 8 + gc;
            float v0 = acc[mi][ni][0], v1 = acc[mi][ni][1];
            float v2 = acc[mi][ni][2], v3 = acc[mi][ni][3];
            if (doEpi) {
                const float b0 = bias[col], b1 = bias[col + 1];
                v0 = elu1(v0 + b0); v1 = elu1(v1 + b1);
                v2 = elu1(v2 + b0); v3 = elu1(v3 + b1);
            }
            *(float2*)&C[(long)row0 * 512 + col]       = make_float2(v0, v1);
            *(float2*)&C[(long)(row0 + 8) * 512 + col] = make_float2(v2, v3);
        }
    }
}

// ---------------- gating softmax ----------------
__global__ void __launch_bounds__(256)
gate_kernel(const float* __restrict__ h, const float* __restrict__ w2,
            const float* __restrict__ b2, float* __restrict__ g)
{
    __shared__ float s[512];
    __shared__ float lg[8];
    const int b = blockIdx.x, tid = threadIdx.x;
    for (int i = tid; i < 512; i += 256) s[i] = h[(long)b * 512 + i];
    __syncthreads();

    const int w = tid >> 5, lane = tid & 31;
    float sum = 0.f;
    for (int i = lane; i < 512; i += 32) sum += s[i] * w2[(long)w * 512 + i];
    #pragma unroll
    for (int o = 16; o > 0; o >>= 1) sum += __shfl_xor_sync(0xffffffffu, sum, o);
    if (lane == 0) lg[w] = sum + b2[w];
    __syncthreads();

    if (tid == 0) {
        float mx = lg[0];
        #pragma unroll
        for (int i = 1; i < 8; i++) mx = fmaxf(mx, lg[i]);
        float ex[8], se = 0.f;
        #pragma unroll
        for (int i = 0; i < 8; i++) { ex[i] = expf(lg[i] - mx); se += ex[i]; }
        float inv = 1.f / se;
        #pragma unroll
        for (int i = 0; i < 8; i++) g[(long)b * 8 + i] = ex[i] * inv;
    }
}

// ---------------- gated blend ----------------
__global__ void __launch_bounds__(256)
blend_kernel(const float* __restrict__ T, const float* __restrict__ g,
             const float* __restrict__ beta, float* __restrict__ out, int doElu)
{
    const int idx = blockIdx.x * 256 + threadIdx.x;
    const int b = idx >> 9, h = idx & 511;
    float sum = 0.f;
    #pragma unroll
    for (int e = 0; e < 8; e++)
        sum += g[b * 8 + e] * (T[((long)e << 18) + idx] + beta[e * 512 + h]);
    out[idx] = doElu ? elu1(sum) : sum;
}

// ---------------- launch ----------------
extern "C" void kernel_launch(void* const* d_in, const int* in_sizes, int n_in,
                              void* d_out, int out_size)
{
    const float* x      = (const float*)d_in[0];
    const float* gw0    = (const float*)d_in[1];
    const float* gb0    = (const float*)d_in[2];
    const float* gw1    = (const float*)d_in[3];
    const float* gb1    = (const float*)d_in[4];
    const float* gw2    = (const float*)d_in[5];
    const float* gb2    = (const float*)d_in[6];
    const float* alpha0 = (const float*)d_in[7];
    const float* beta0  = (const float*)d_in[8];
    const float* alpha1 = (const float*)d_in[9];
    const float* beta1  = (const float*)d_in[10];
    const float* alpha2 = (const float*)d_in[11];
    const float* beta2  = (const float*)d_in[12];
    float* out = (float*)d_out;

    float *h1, *h2, *gp, *T, *e1, *e2;
    cudaGetSymbolAddress((void**)&h1, d_h1);
    cudaGetSymbolAddress((void**)&h2, d_h2);
    cudaGetSymbolAddress((void**)&gp, d_g);
    cudaGetSymbolAddress((void**)&T,  d_T);
    cudaGetSymbolAddress((void**)&e1, d_e1);
    cudaGetSymbolAddress((void**)&e2, d_e2);

    __nv_bfloat16 *xhi, *xlo, *ahi, *alo, *g0hi, *g0lo, *g1hi, *g1lo;
    __nv_bfloat16 *w0hi, *w0lo, *w1hi, *w1lo, *w2hi, *w2lo;
    cudaGetSymbolAddress((void**)&xhi,  d_xhi);  cudaGetSymbolAddress((void**)&xlo,  d_xlo);
    cudaGetSymbolAddress((void**)&ahi,  d_ahi);  cudaGetSymbolAddress((void**)&alo,  d_alo);
    cudaGetSymbolAddress((void**)&g0hi, d_g0hi); cudaGetSymbolAddress((void**)&g0lo, d_g0lo);
    cudaGetSymbolAddress((void**)&g1hi, d_g1hi); cudaGetSymbolAddress((void**)&g1lo, d_g1lo);
    cudaGetSymbolAddress((void**)&w0hi, d_w0hi); cudaGetSymbolAddress((void**)&w0lo, d_w0lo);
    cudaGetSymbolAddress((void**)&w1hi, d_w1hi); cudaGetSymbolAddress((void**)&w1lo, d_w1lo);
    cudaGetSymbolAddress((void**)&w2hi, d_w2hi); cudaGetSymbolAddress((void**)&w2lo, d_w2lo);

    const int SMEM_SZ = 3 * 32768;  // 3-stage double tile (A 16KB + B 16KB per stage)
    cudaFuncSetAttribute(tgemm_mma, cudaFuncAttributeMaxDynamicSharedMemorySize, SMEM_SZ);

    const int NSMALL4 = (512 * 512) / 4;
    const int NBIG4   = (8 * 512 * 512) / 4;
    const long sW = 512L * 512, sC = 512L * 512;
    dim3 g1(4, 4, 1), g8(4, 4, 8);

    // split conversions
    conv_split<<<NSMALL4 / 256, 256>>>((const float4*)x,   (uint2*)xhi,  (uint2*)xlo,  NSMALL4);
    conv_split<<<NSMALL4 / 256, 256>>>((const float4*)gw0, (uint2*)g0hi, (uint2*)g0lo, NSMALL4);
    conv_split<<<NSMALL4 / 256, 256>>>((const float4*)gw1, (uint2*)g1hi, (uint2*)g1lo, NSMALL4);
    conv_split<<<NBIG4 / 256, 256>>>((const float4*)alpha0, (uint2*)w0hi, (uint2*)w0lo, NBIG4);
    conv_split<<<NBIG4 / 256, 256>>>((const float4*)alpha1, (uint2*)w1hi, (uint2*)w1lo, NBIG4);
    conv_split<<<NBIG4 / 256, 256>>>((const float4*)alpha2, (uint2*)w2hi, (uint2*)w2lo, NBIG4);

    // gating MLP
    tgemm_mma<<<g1, 256, SMEM_SZ>>>(xhi, xlo, g0hi, g0lo, gb0, h1, 0, 0, 1);
    conv_split<<<NSMALL4 / 256, 256>>>((const float4*)h1, (uint2*)ahi, (uint2*)alo, NSMALL4);
    tgemm_mma<<<g1, 256, SMEM_SZ>>>(ahi, alo, g1hi, g1lo, gb1, h2, 0, 0, 1);
    gate_kernel<<<BSZ, 256>>>(h2, gw2, gb2, gp);

    // expert layer 1
    tgemm_mma<<<g8, 256, SMEM_SZ>>>(xhi, xlo, w0hi, w0lo, nullptr, T, sW, sC, 0);
    blend_kernel<<<(BSZ * HD) / 256, 256>>>(T, gp, beta0, e1, 1);

    // expert layer 2
    conv_split<<<NSMALL4 / 256, 256>>>((const float4*)e1, (uint2*)ahi, (uint2*)alo, NSMALL4);
    tgemm_mma<<<g8, 256, SMEM_SZ>>>(ahi, alo, w1hi, w1lo, nullptr, T, sW, sC, 0);
    blend_kernel<<<(BSZ * HD) / 256, 256>>>(T, gp, beta1, e2, 1);

    // expert layer 3
    conv_split<<<NSMALL4 / 256, 256>>>((const float4*)e2, (uint2*)ahi, (uint2*)alo, NSMALL4);
    tgemm_mma<<<g8, 256, SMEM_SZ>>>(ahi, alo, w2hi, w2lo, nullptr, T, sW, sC, 0);
    blend_kernel<<<(BSZ * OD) / 256, 256>>>(T, gp, beta2, out, 0);
}

// round 4
// speedup vs baseline: 2.2681x; 1.1772x over previous
#include <cuda_runtime.h>
#include <cuda_bf16.h>
#include <math.h>
#include <cstdint>

#define BSZ 512
#define FD  512
#define HD  512
#define ED  8
#define OD  512

// ---------------- scratch (device globals; allocation is forbidden) ----------------
__device__ float d_h2[BSZ * HD];
__device__ float d_g [BSZ * ED];
__device__ float d_T [ED * BSZ * HD];

__device__ __align__(16) __nv_bfloat16 d_xhi[BSZ * FD], d_xlo[BSZ * FD];
__device__ __align__(16) __nv_bfloat16 d_ahi[BSZ * FD], d_alo[BSZ * FD];
__device__ __align__(16) __nv_bfloat16 d_g0hi[HD * FD], d_g0lo[HD * FD];
__device__ __align__(16) __nv_bfloat16 d_g1hi[HD * HD], d_g1lo[HD * HD];
__device__ __align__(16) __nv_bfloat16 d_w0hi[ED * HD * FD], d_w0lo[ED * HD * FD];
__device__ __align__(16) __nv_bfloat16 d_w1hi[ED * HD * HD], d_w1lo[ED * HD * HD];
__device__ __align__(16) __nv_bfloat16 d_w2hi[ED * OD * HD], d_w2lo[ED * OD * HD];

__device__ __forceinline__ float elu1(float v) { return v > 0.f ? v : expm1f(v); }

__device__ __forceinline__ uint32_t smem_u32(const void* p) {
    uint32_t a;
    asm("{ .reg .u64 t; cvta.to.shared.u64 t, %1; cvt.u32.u64 %0, t; }" : "=r"(a) : "l"(p));
    return a;
}

#define CP16(dst, src) \
    asm volatile("cp.async.cg.shared.global [%0], [%1], 16;" :: "r"(dst), "l"(src))

#define LDSM4(r, addr) \
    asm volatile("ldmatrix.sync.aligned.m8n8.x4.shared.b16 {%0,%1,%2,%3}, [%4];" \
                 : "=r"((r)[0]), "=r"((r)[1]), "=r"((r)[2]), "=r"((r)[3]) : "r"(addr))

#define MMA16816(d, a, b0, b1) \
    asm volatile("mma.sync.aligned.m16n8k16.row.col.f32.bf16.bf16.f32 " \
                 "{%0,%1,%2,%3},{%4,%5,%6,%7},{%8,%9},{%0,%1,%2,%3};" \
                 : "+f"((d)[0]), "+f"((d)[1]), "+f"((d)[2]), "+f"((d)[3]) \
                 : "r"((a)[0]), "r"((a)[1]), "r"((a)[2]), "r"((a)[3]), "r"(b0), "r"(b1))

__device__ __forceinline__ uint32_t pack_bf16x2(float a, float b) {
    uint32_t r;
    asm("cvt.rn.bf16x2.f32 %0, %1, %2;" : "=r"(r) : "f"(b), "f"(a));
    return r;
}

// ---------------- split-conversion: fp32 -> (hi, lo) bf16 ----------------
__global__ void __launch_bounds__(256)
conv_split(const float4* __restrict__ in, uint2* __restrict__ hi, uint2* __restrict__ lo, int n4) {
    int i = blockIdx.x * 256 + threadIdx.x;
    if (i >= n4) return;
    float4 v = in[i];
    __nv_bfloat16 h0 = __float2bfloat16(v.x), h1 = __float2bfloat16(v.y);
    __nv_bfloat16 h2 = __float2bfloat16(v.z), h3 = __float2bfloat16(v.w);
    __nv_bfloat16 l0 = __float2bfloat16(v.x - __bfloat162float(h0));
    __nv_bfloat16 l1 = __float2bfloat16(v.y - __bfloat162float(h1));
    __nv_bfloat16 l2 = __float2bfloat16(v.z - __bfloat162float(h2));
    __nv_bfloat16 l3 = __float2bfloat16(v.w - __bfloat162float(h3));
    uint2 H, L;
    H.x = (uint32_t)__bfloat16_as_ushort(h0) | ((uint32_t)__bfloat16_as_ushort(h1) << 16);
    H.y = (uint32_t)__bfloat16_as_ushort(h2) | ((uint32_t)__bfloat16_as_ushort(h3) << 16);
    L.x = (uint32_t)__bfloat16_as_ushort(l0) | ((uint32_t)__bfloat16_as_ushort(l1) << 16);
    L.y = (uint32_t)__bfloat16_as_ushort(l2) | ((uint32_t)__bfloat16_as_ushort(l3) << 16);
    hi[i] = H; lo[i] = L;
}

// ---------------- fused 3-pass split GEMM ----------------
// acc = Ahi·Bhi^T + Alo·Bhi^T + Ahi·Blo^T over K=512, tile 128x128, BK=64.
// Per stage loads 4 tiles (Ahi,Alo,Bhi,Blo) = 64KB; 3 stages (192KB smem); 8 K-iters.
// mode: 0 = plain fp32 out; 1 = bias+elu fp32 out; 2 = bias+elu, split bf16 hi/lo out.
__global__ void __launch_bounds__(256)
tgemm_fused(const __nv_bfloat16* __restrict__ Axhi, const __nv_bfloat16* __restrict__ Axlo,
            const __nv_bfloat16* __restrict__ Bwhi, const __nv_bfloat16* __restrict__ Bwlo,
            const float* __restrict__ bias, float* __restrict__ C,
            __nv_bfloat16* __restrict__ Ohi, __nv_bfloat16* __restrict__ Olo,
            long strideW, long strideC, int mode)
{
    extern __shared__ __align__(128) char smem[];
    const uint32_t sb = smem_u32(smem);
    const int tid = threadIdx.x;
    const int wid = tid >> 5, lane = tid & 31;
    const int e = blockIdx.z;
    const int bm = blockIdx.y * 128, bn = blockIdx.x * 128;
    Bwhi += (long)e * strideW;
    Bwlo += (long)e * strideW;
    C    += (long)e * strideC;

    const int lsub = tid >> 3;   // 0..31
    const int lc16 = tid & 7;

    const __nv_bfloat16* tp[4] = { Axhi, Axlo, Bwhi, Bwlo };
    const int toff[4] = { bm, bm, bn, bn };

    // stage layout: [Ahi 16K][Alo 16K][Bhi 16K][Blo 16K]; stage stride 64K
    auto load_stage = [&](int kc, int buf) {
        const int k0 = kc << 6;
        const uint32_t base = sb + (uint32_t)buf * 65536u;
        #pragma unroll
        for (int t = 0; t < 4; t++) {
            const __nv_bfloat16* P = tp[t];
            #pragma unroll
            for (int it = 0; it < 4; it++) {
                const int row = it * 32 + lsub;
                const uint32_t dst = base + (uint32_t)t * 16384u
                                   + (uint32_t)(row * 128 + ((lc16 ^ (row & 7)) << 4));
                CP16(dst, P + (long)(toff[t] + row) * 512 + k0 + lc16 * 8);
            }
        }
    };

    // warp layout: 4 warps along M, 2 along N; warp tile 32(M) x 64(N)
    const int warpM = wid & 3, warpN = wid >> 2;
    const int arow = warpM * 32 + (lane & 15);
    const uint32_t aswz = (uint32_t)(arow & 7);
    const uint32_t ahalf = (uint32_t)(lane >> 4);
    const int q = lane >> 3;
    const int brow_base = warpN * 64 + ((q >> 1) << 3) + (lane & 7);
    const uint32_t bk = (uint32_t)(q & 1);

    float acc[2][8][4] = {};

    load_stage(0, 0);
    asm volatile("cp.async.commit_group;" ::: "memory");
    load_stage(1, 1);
    asm volatile("cp.async.commit_group;" ::: "memory");

    for (int c = 0; c < 8; c++) {
        if (c < 7) asm volatile("cp.async.wait_group 1;" ::: "memory");
        else       asm volatile("cp.async.wait_group 0;" ::: "memory");
        __syncthreads();
        if (c + 2 < 8) {
            load_stage(c + 2, (c + 2) % 3);
            asm volatile("cp.async.commit_group;" ::: "memory");
        }

        const uint32_t S   = sb + (uint32_t)(c % 3) * 65536u;
        const uint32_t Ahi = S, Alo = S + 16384u, Bhi = S + 32768u, Blo = S + 49152u;

        #pragma unroll
        for (int ks = 0; ks < 4; ks++) {
            const uint32_t achunk = (((uint32_t)(ks << 1) + ahalf) ^ aswz) << 4;
            uint32_t ah[2][4], al[2][4];
            #pragma unroll
            for (int mi = 0; mi < 2; mi++) {
                const uint32_t roff = (uint32_t)((arow + mi * 16) * 128);
                LDSM4(ah[mi], Ahi + roff + achunk);
                LDSM4(al[mi], Alo + roff + achunk);
            }
            uint32_t b[4][4];
            #pragma unroll
            for (int np = 0; np < 4; np++) {
                const int brow = brow_base + np * 16;
                const uint32_t boff = (uint32_t)(brow * 128)
                                    + ((((uint32_t)(ks << 1) + bk) ^ (uint32_t)(brow & 7)) << 4);
                LDSM4(b[np], Bhi + boff);
            }
            #pragma unroll
            for (int mi = 0; mi < 2; mi++)
                #pragma unroll
                for (int ni = 0; ni < 8; ni++) {
                    MMA16816(acc[mi][ni], ah[mi], b[ni >> 1][(ni & 1) * 2],
                             b[ni >> 1][(ni & 1) * 2 + 1]);
                    MMA16816(acc[mi][ni], al[mi], b[ni >> 1][(ni & 1) * 2],
                             b[ni >> 1][(ni & 1) * 2 + 1]);
                }
            #pragma unroll
            for (int np = 0; np < 4; np++) {
                const int brow = brow_base + np * 16;
                const uint32_t boff = (uint32_t)(brow * 128)
                                    + ((((uint32_t)(ks << 1) + bk) ^ (uint32_t)(brow & 7)) << 4);
                LDSM4(b[np], Blo + boff);
            }
            #pragma unroll
            for (int mi = 0; mi < 2; mi++)
                #pragma unroll
                for (int ni = 0; ni < 8; ni++)
                    MMA16816(acc[mi][ni], ah[mi], b[ni >> 1][(ni & 1) * 2],
                             b[ni >> 1][(ni & 1) * 2 + 1]);
        }
        __syncthreads();
    }

    // epilogue
    const int gr = lane >> 2, gc = (lane & 3) * 2;
    #pragma unroll
    for (int mi = 0; mi < 2; mi++) {
        const int row0 = bm + warpM * 32 + mi * 16 + gr;
        #pragma unroll
        for (int ni = 0; ni < 8; ni++) {
            const int col = bn + warpN * 64 + ni * 8 + gc;
            float v0 = acc[mi][ni][0], v1 = acc[mi][ni][1];
            float v2 = acc[mi][ni][2], v3 = acc[mi][ni][3];
            if (mode != 0) {
                const float b0 = bias[col], b1 = bias[col + 1];
                v0 = elu1(v0 + b0); v1 = elu1(v1 + b1);
                v2 = elu1(v2 + b0); v3 = elu1(v3 + b1);
            }
            if (mode == 2) {
                // split write: hi = bf16(v), lo = bf16(v - hi)
                float h0f = __bfloat162float(__float2bfloat16(v0));
                float h1f = __bfloat162float(__float2bfloat16(v1));
                float h2f = __bfloat162float(__float2bfloat16(v2));
                float h3f = __bfloat162float(__float2bfloat16(v3));
                *(uint32_t*)&Ohi[(long)row0 * 512 + col]       = pack_bf16x2(h0f, h1f);
                *(uint32_t*)&Olo[(long)row0 * 512 + col]       = pack_bf16x2(v0 - h0f, v1 - h1f);
                *(uint32_t*)&Ohi[(long)(row0 + 8) * 512 + col] = pack_bf16x2(h2f, h3f);
                *(uint32_t*)&Olo[(long)(row0 + 8) * 512 + col] = pack_bf16x2(v2 - h2f, v3 - h3f);
            } else {
                *(float2*)&C[(long)row0 * 512 + col]       = make_float2(v0, v1);
                *(float2*)&C[(long)(row0 + 8) * 512 + col] = make_float2(v2, v3);
            }
        }
    }
}

// ---------------- gating softmax ----------------
__global__ void __launch_bounds__(256)
gate_kernel(const float* __restrict__ h, const float* __restrict__ w2,
            const float* __restrict__ b2, float* __restrict__ g)
{
    __shared__ float s[512];
    __shared__ float lg[8];
    const int b = blockIdx.x, tid = threadIdx.x;
    for (int i = tid; i < 512; i += 256) s[i] = h[(long)b * 512 + i];
    __syncthreads();

    const int w = tid >> 5, lane = tid & 31;
    float sum = 0.f;
    for (int i = lane; i < 512; i += 32) sum += s[i] * w2[(long)w * 512 + i];
    #pragma unroll
    for (int o = 16; o > 0; o >>= 1) sum += __shfl_xor_sync(0xffffffffu, sum, o);
    if (lane == 0) lg[w] = sum + b2[w];
    __syncthreads();

    if (tid == 0) {
        float mx = lg[0];
        #pragma unroll
        for (int i = 1; i < 8; i++) mx = fmaxf(mx, lg[i]);
        float ex[8], se = 0.f;
        #pragma unroll
        for (int i = 0; i < 8; i++) { ex[i] = expf(lg[i] - mx); se += ex[i]; }
        float inv = 1.f / se;
        #pragma unroll
        for (int i = 0; i < 8; i++) g[(long)b * 8 + i] = ex[i] * inv;
    }
}

// ---------------- gated blend (float4) ----------------
// mode 0: out fp32, no elu (final). mode 1: elu then split bf16 hi/lo.
__global__ void __launch_bounds__(256)
blend_kernel(const float4* __restrict__ T4, const float* __restrict__ g,
             const float4* __restrict__ beta4, float* __restrict__ out,
             __nv_bfloat16* __restrict__ Ohi, __nv_bfloat16* __restrict__ Olo, int mode)
{
    const int i4 = blockIdx.x * 256 + threadIdx.x;     // 65536 float4s
    const int base = i4 << 2;
    const int b = base >> 9, h4 = (base & 511) >> 2;
    float4 sum = make_float4(0.f, 0.f, 0.f, 0.f);
    #pragma unroll
    for (int e = 0; e < 8; e++) {
        const float ge = g[b * 8 + e];
        const float4 t = T4[(e << 16) + i4];
        const float4 be = beta4[(e << 7) + h4];
        sum.x += ge * (t.x + be.x); sum.y += ge * (t.y + be.y);
        sum.z += ge * (t.z + be.z); sum.w += ge * (t.w + be.w);
    }
    if (mode == 0) {
        ((float4*)out)[i4] = sum;
    } else {
        sum.x = elu1(sum.x); sum.y = elu1(sum.y); sum.z = elu1(sum.z); sum.w = elu1(sum.w);
        float h0 = __bfloat162float(__float2bfloat16(sum.x));
        float h1 = __bfloat162float(__float2bfloat16(sum.y));
        float h2 = __bfloat162float(__float2bfloat16(sum.z));
        float h3 = __bfloat162float(__float2bfloat16(sum.w));
        uint2 H, L;
        H.x = pack_bf16x2(h0, h1); H.y = pack_bf16x2(h2, h3);
        L.x = pack_bf16x2(sum.x - h0, sum.y - h1);
        L.y = pack_bf16x2(sum.z - h2, sum.w - h3);
        ((uint2*)Ohi)[i4] = H;
        ((uint2*)Olo)[i4] = L;
    }
}

// ---------------- launch ----------------
extern "C" void kernel_launch(void* const* d_in, const int* in_sizes, int n_in,
                              void* d_out, int out_size)
{
    const float* x      = (const float*)d_in[0];
    const float* gw0    = (const float*)d_in[1];
    const float* gb0    = (const float*)d_in[2];
    const float* gw1    = (const float*)d_in[3];
    const float* gb1    = (const float*)d_in[4];
    const float* gw2    = (const float*)d_in[5];
    const float* gb2    = (const float*)d_in[6];
    const float* alpha0 = (const float*)d_in[7];
    const float* beta0  = (const float*)d_in[8];
    const float* alpha1 = (const float*)d_in[9];
    const float* beta1  = (const float*)d_in[10];
    const float* alpha2 = (const float*)d_in[11];
    const float* beta2  = (const float*)d_in[12];
    float* out = (float*)d_out;

    float *h2, *gp, *T;
    cudaGetSymbolAddress((void**)&h2, d_h2);
    cudaGetSymbolAddress((void**)&gp, d_g);
    cudaGetSymbolAddress((void**)&T,  d_T);

    __nv_bfloat16 *xhi, *xlo, *ahi, *alo, *g0hi, *g0lo, *g1hi, *g1lo;
    __nv_bfloat16 *w0hi, *w0lo, *w1hi, *w1lo, *w2hi, *w2lo;
    cudaGetSymbolAddress((void**)&xhi,  d_xhi);  cudaGetSymbolAddress((void**)&xlo,  d_xlo);
    cudaGetSymbolAddress((void**)&ahi,  d_ahi);  cudaGetSymbolAddress((void**)&alo,  d_alo);
    cudaGetSymbolAddress((void**)&g0hi, d_g0hi); cudaGetSymbolAddress((void**)&g0lo, d_g0lo);
    cudaGetSymbolAddress((void**)&g1hi, d_g1hi); cudaGetSymbolAddress((void**)&g1lo, d_g1lo);
    cudaGetSymbolAddress((void**)&w0hi, d_w0hi); cudaGetSymbolAddress((void**)&w0lo, d_w0lo);
    cudaGetSymbolAddress((void**)&w1hi, d_w1hi); cudaGetSymbolAddress((void**)&w1lo, d_w1lo);
    cudaGetSymbolAddress((void**)&w2hi, d_w2hi); cudaGetSymbolAddress((void**)&w2lo, d_w2lo);

    const int SMEM_SZ = 3 * 65536;  // 3 stages x (Ahi+Alo+Bhi+Blo)
    cudaFuncSetAttribute(tgemm_fused, cudaFuncAttributeMaxDynamicSharedMemorySize, SMEM_SZ);

    const int NSMALL4 = (512 * 512) / 4;
    const int NBIG4   = (8 * 512 * 512) / 4;
    const long sW = 512L * 512, sC = 512L * 512;
    dim3 g1(4, 4, 1), g8(4, 4, 8);
    const int BLEND_B = (BSZ * HD / 4) / 256;  // 256 blocks

    // split conversions (inputs + weights)
    conv_split<<<NSMALL4 / 256, 256>>>((const float4*)x,   (uint2*)xhi,  (uint2*)xlo,  NSMALL4);
    conv_split<<<NSMALL4 / 256, 256>>>((const float4*)gw0, (uint2*)g0hi, (uint2*)g0lo, NSMALL4);
    conv_split<<<NSMALL4 / 256, 256>>>((const float4*)gw1, (uint2*)g1hi, (uint2*)g1lo, NSMALL4);
    conv_split<<<NBIG4 / 256, 256>>>((const float4*)alpha0, (uint2*)w0hi, (uint2*)w0lo, NBIG4);
    conv_split<<<NBIG4 / 256, 256>>>((const float4*)alpha1, (uint2*)w1hi, (uint2*)w1lo, NBIG4);
    conv_split<<<NBIG4 / 256, 256>>>((const float4*)alpha2, (uint2*)w2hi, (uint2*)w2lo, NBIG4);

    // gating MLP (layer1 writes split bf16 directly; layer2 fp32 for softmax)
    tgemm_fused<<<g1, 256, SMEM_SZ>>>(xhi, xlo, g0hi, g0lo, gb0, nullptr, ahi, alo, 0, 0, 2);
    tgemm_fused<<<g1, 256, SMEM_SZ>>>(ahi, alo, g1hi, g1lo, gb1, h2, nullptr, nullptr, 0, 0, 1);
    gate_kernel<<<BSZ, 256>>>(h2, gw2, gb2, gp);

    // expert layer 1
    tgemm_fused<<<g8, 256, SMEM_SZ>>>(xhi, xlo, w0hi, w0lo, nullptr, T, nullptr, nullptr, sW, sC, 0);
    blend_kernel<<<BLEND_B, 256>>>((const float4*)T, gp, (const float4*)beta0, nullptr, ahi, alo, 1);

    // expert layer 2
    tgemm_fused<<<g8, 256, SMEM_SZ>>>(ahi, alo, w1hi, w1lo, nullptr, T, nullptr, nullptr, sW, sC, 0);
    blend_kernel<<<BLEND_B, 256>>>((const float4*)T, gp, (const float4*)beta1, nullptr, ahi, alo, 1);

    // expert layer 3 (final: fp32, no activation)
    tgemm_fused<<<g8, 256, SMEM_SZ>>>(ahi, alo, w2hi, w2lo, nullptr, T, nullptr, nullptr, sW, sC, 0);
    blend_kernel<<<BLEND_B, 256>>>((const float4*)T, gp, (const float4*)beta2, out, nullptr, nullptr, 0);
}